// round 11
// baseline (speedup 1.0000x reference)
#include <cuda_runtime.h>

// Fixed problem shape: B=8, H=W=512, C=32, n_segments=256
#define B_    8
#define HW_   (512 * 512)
#define C_    32
#define S_    256
#define CPB_  38                  // CTAs per batch
#define NCTA  (B_ * CPB_)         // 304 = 2 x 152 SMs (GB300) -> one exact wave
#define CW    16                  // consumer warps
#define TPB   ((CW + 1) * 32)     // 544: 16 consumer warps + 1 producer warp
#define SEGW  (S_ / CW)           // 16 segments owned per consumer warp
#define BP    64                  // pixels per stage (8 KB image + 256 B ids)
#define UPB   (HW_ / BP)          // 4096 stage-units per batch
#define D     4                   // pipeline depth

#define IMG_BYTES (BP * C_ * 4)   // 8192
#define IDS_BYTES (BP * 4)        // 256
#define TX_BYTES  (IMG_BYTES + IDS_BYTES)

// Per-CTA partials (.x = sum, .y = count as float; counts << 2^24 -> exact).
// Fully overwritten every launch -> no zeroing, replay-safe, zero atomics.
__device__ float2 g_part[(size_t)NCTA * S_ * C_];   // ~19.9 MB

__device__ __forceinline__ unsigned smem_u32(const void* p) {
    return (unsigned)__cvta_generic_to_shared(p);
}
__device__ __forceinline__ void mbar_init(unsigned a, unsigned cnt) {
    asm volatile("mbarrier.init.shared.b64 [%0], %1;" :: "r"(a), "r"(cnt) : "memory");
}
__device__ __forceinline__ void mbar_expect_tx(unsigned a, unsigned tx) {
    asm volatile("mbarrier.arrive.expect_tx.shared.b64 _, [%0], %1;" :: "r"(a), "r"(tx) : "memory");
}
__device__ __forceinline__ void mbar_arrive(unsigned a) {
    asm volatile("mbarrier.arrive.shared.b64 _, [%0];" :: "r"(a) : "memory");
}
__device__ __forceinline__ void mbar_wait_acq(unsigned a, unsigned ph) {
    asm volatile(
        "{\n\t.reg .pred P;\n\t"
        "WL%=:\n\tmbarrier.try_wait.parity.acquire.cta.shared::cta.b64 P, [%0], %1, 0x989680;\n\t"
        "@P bra WD%=;\n\tbra WL%=;\n\tWD%=:\n\t}"
        :: "r"(a), "r"(ph) : "memory");
}
__device__ __forceinline__ void mbar_wait_rlx(unsigned a, unsigned ph) {
    asm volatile(
        "{\n\t.reg .pred P;\n\t"
        "WL%=:\n\tmbarrier.try_wait.parity.relaxed.cta.shared::cta.b64 P, [%0], %1, 0x989680;\n\t"
        "@P bra WD%=;\n\tbra WL%=;\n\tWD%=:\n\t}"
        :: "r"(a), "r"(ph) : "memory");
}
__device__ __forceinline__ void bulk_g2s(unsigned dst, const void* src,
                                         unsigned bytes, unsigned mbar) {
    asm volatile(
        "cp.async.bulk.shared::cta.global.mbarrier::complete_tx::bytes [%0], [%1], %2, [%3];"
        :: "r"(dst), "l"(src), "r"(bytes), "r"(mbar) : "memory");
}

// 4-wide consume of one 32-pixel ballot group. All shfls / buf loads / bin
// loads are issued as independent batches before any dependent use -> the
// ~90 cyc dependent chain is amortized over up to 4 pixels.
__device__ __forceinline__ void consume_group(unsigned m, int id, int lo, int lane,
                                              const float* __restrict__ buf32,
                                              float2* __restrict__ wbin) {
    while (m) {
        int j[4]; bool on[4];
        #pragma unroll
        for (int t = 0; t < 4; t++) {
            on[t] = (m != 0);
            j[t]  = on[t] ? (__ffs(m) - 1) : 0;
            m    &= m - 1;
        }
        int sg[4]; float v[4]; float2 b[4];
        #pragma unroll
        for (int t = 0; t < 4; t++)
            sg[t] = __shfl_sync(0xffffffffu, id, j[t]) - lo;   // 4 independent shfls
        #pragma unroll
        for (int t = 0; t < 4; t++)
            v[t] = on[t] ? buf32[j[t] * C_ + lane] : 0.f;       // 4 independent LDS
        #pragma unroll
        for (int t = 0; t < 4; t++)
            b[t] = on[t] ? wbin[sg[t] * C_ + lane] : make_float2(0.f, 0.f);
        #pragma unroll
        for (int t = 0; t < 4; t++)
            if (on[t]) {
                // Same-thread smem ops are in order, so duplicate segments in
                // one batch still accumulate correctly (RAW serializes).
                float2 nb; nb.x = b[t].x + v[t];
                nb.y = b[t].y + ((v[t] != 0.f) ? 1.f : 0.f);
                // Re-read if an earlier t in this batch wrote the same bin.
                #pragma unroll
                for (int u = 0; u < 4; u++) { } // (ordering handled by LSU)
                float2 cur = wbin[sg[t] * C_ + lane];
                cur.x += v[t]; cur.y += (v[t] != 0.f) ? 1.f : 0.f;
                wbin[sg[t] * C_ + lane] = cur;
            }
    }
}

// ---------------------------------------------------------------------------
// k_accum: warp-specialized mbarrier pipeline. Producer warp streams the image
// sequentially via cp.async.bulk into a depth-4 stage ring; 16 consumer warps
// accumulate into warp-private float2 smem bins (no atomics, no __syncthreads
// in the loop). smem: bins 64 KB + 4 x (8 KB + 256 B) stages + barriers
// = ~97 KB -> 2 CTAs/SM, full 304-CTA wave resident.
// ---------------------------------------------------------------------------
__global__ void __launch_bounds__(TPB, 2) k_accum(const float* __restrict__ img,
                                                  const int* __restrict__ slic) {
    extern __shared__ char smem[];
    float2* s_bin = (float2*)smem;                               // 65536 B
    float*  s_buf = (float*)(smem + 65536);                      // D*8192 = 32768 B
    int*    s_ids = (int*)(smem + 65536 + 32768);                // D*256  = 1024 B
    const unsigned mbase = smem_u32(smem + 65536 + 32768 + 1024);

    const int tid = threadIdx.x, w = tid >> 5, lane = tid & 31;

    #pragma unroll
    for (int i = tid; i < S_ * C_; i += TPB) s_bin[i] = make_float2(0.f, 0.f);
    if (tid == 0) {
        #pragma unroll
        for (int i = 0; i < D; i++) {
            mbar_init(mbase + i * 8, 1);            // full: producer expect_tx
            mbar_init(mbase + (D + i) * 8, CW);     // empty: one arrive per consumer warp
        }
    }
    __syncthreads();

    // Per-batch contiguous unit range (107 or 108 units), never straddles batch.
    const int batch = blockIdx.x / CPB_;
    const int c     = blockIdx.x % CPB_;
    const int u0 = batch * UPB + (c * UPB) / CPB_;
    const int nb = batch * UPB + ((c + 1) * UPB) / CPB_ - u0;

    if (w == CW) {
        // ----- producer warp (lane 0 only) -----
        if (lane == 0) {
            int st = 0, ph = 1;                     // phase 1: first D waits pass free
            for (int g = 0; g < nb; g++) {
                mbar_wait_rlx(mbase + (D + st) * 8, (unsigned)ph);
                unsigned fb = mbase + st * 8;
                mbar_expect_tx(fb, TX_BYTES);
                bulk_g2s(smem_u32(s_buf + st * BP * C_),
                         img + (size_t)(u0 + g) * BP * C_, IMG_BYTES, fb);
                bulk_g2s(smem_u32(s_ids + st * BP),
                         slic + (size_t)(u0 + g) * BP, IDS_BYTES, fb);
                if (++st == D) { st = 0; ph ^= 1; }
            }
        }
    } else {
        // ----- consumer warps -----
        const int lo = w * SEGW;
        float2* wbin = s_bin + lo * C_;
        int st = 0, ph = 0;

        for (int g = 0; g < nb; g++) {
            mbar_wait_acq(mbase + st * 8, (unsigned)ph);
            const float* buf = s_buf + st * BP * C_;
            const int*   ids = s_ids + st * BP;

            // Load + ballot both 32-px groups up front (overlaps consume).
            int id0 = ids[lane]      - 1;           // 1-based; 0 -> -1 dropped
            int id1 = ids[32 + lane] - 1;
            unsigned m0 = __ballot_sync(0xffffffffu,
                                        ((unsigned)(id0 - lo)) < (unsigned)SEGW);
            unsigned m1 = __ballot_sync(0xffffffffu,
                                        ((unsigned)(id1 - lo)) < (unsigned)SEGW);

            consume_group(m0, id0, lo, lane, buf,            wbin);
            consume_group(m1, id1, lo, lane, buf + 32 * C_,  wbin);

            if (lane == 0) mbar_arrive(mbase + (D + st) * 8);  // release stage
            if (++st == D) { st = 0; ph ^= 1; }
        }

        // Write this warp's partials (own bins -> no sync needed).
        const size_t ob = (size_t)blockIdx.x * S_ * C_;
        #pragma unroll
        for (int sgl = 0; sgl < SEGW; sgl++)
            g_part[ob + (lo + sgl) * C_ + lane] = wbin[sgl * C_ + lane];
    }
}

// ---------------------------------------------------------------------------
// k_final: reduce the 38 per-batch CTA partials for each (b, s), divide.
// 8 warps split the chunk list (independent loads -> MLP ~5 per warp),
// smem combine in fixed order -> deterministic. 0/0 -> NaN matches reference.
// ---------------------------------------------------------------------------
__global__ void __launch_bounds__(256) k_final(float* __restrict__ out) {
    __shared__ float2 red[8][32];
    int bs = blockIdx.x, b = bs >> 8, s = bs & (S_ - 1);
    int lane = threadIdx.x & 31, w = threadIdx.x >> 5;

    float2 acc = make_float2(0.f, 0.f);
    #pragma unroll
    for (int k = w; k < CPB_; k += 8) {
        float2 p = g_part[((size_t)(b * CPB_ + k) * S_ + s) * C_ + lane];
        acc.x += p.x; acc.y += p.y;
    }
    red[w][lane] = acc;
    __syncthreads();
    if (w == 0) {
        float sum = 0.f, cnt = 0.f;
        #pragma unroll
        for (int i = 0; i < 8; i++) { sum += red[i][lane].x; cnt += red[i][lane].y; }
        out[((size_t)s * B_ + b) * C_ + lane] = sum / cnt;
    }
}

// ---------------------------------------------------------------------------
// d_in[0] = image_output [8,512,512,32] f32
// d_in[1] = slic_output  [8,512,512,1]  i32
// d_in[2] = n_segments (fixed 256, compiled in)
// d_out   = [256, 8, 32] f32
// ---------------------------------------------------------------------------
extern "C" void kernel_launch(void* const* d_in, const int* in_sizes, int n_in,
                              void* d_out, int out_size) {
    const float* img  = (const float*)d_in[0];
    const int*   slic = (const int*)d_in[1];
    float*       out  = (float*)d_out;

    const int smem_bytes = 65536 + 32768 + 1024 + 64;   // 99392 -> 2 CTAs/SM
    cudaFuncSetAttribute(k_accum, cudaFuncAttributeMaxDynamicSharedMemorySize, smem_bytes);

    k_accum<<<NCTA, TPB, smem_bytes>>>(img, slic);
    k_final<<<B_ * S_, 256>>>(out);
}